// round 4
// baseline (speedup 1.0000x reference)
#include <cuda_runtime.h>

#define BATCH 64
#define TT    200
#define NUM_C 2000
#define DIM   128
#define MM    50
#define MP    56          // M padded; rows 50..55 have w=0 (inert)
#define NX    4000        // distinct x = skill + 2000*answer

typedef unsigned long long u64;

// ---------------- packed f32x2 helpers (FFMA2: PTX-only, 2x fp32 tput) ----
__device__ __forceinline__ u64 pk2(float lo, float hi) {
    u64 r; asm("mov.b64 %0, {%1, %2};" : "=l"(r) : "f"(lo), "f"(hi)); return r;
}
__device__ __forceinline__ void upk2(float& lo, float& hi, u64 v) {
    asm("mov.b64 {%0, %1}, %2;" : "=f"(lo), "=f"(hi) : "l"(v));
}
__device__ __forceinline__ u64 fma2(u64 a, u64 b, u64 c) {
    u64 d; asm("fma.rn.f32x2 %0, %1, %2, %3;" : "=l"(d) : "l"(a), "l"(b), "l"(c)); return d;
}

// ---------------- scratch (device globals; no allocation allowed) ----------
__device__ __align__(16) float g_w[NUM_C * MP];       // softmax(k·Mk^T) per skill id
__device__ __align__(16) float g_ea[NX * 256];        // [x][0:128]=e, [128:256]=a
__device__ __align__(16) float g_kf[NUM_C * DIM];     // k-part of f GEMM + f_b folded
__device__ __align__(16) float g_reads[BATCH * TT * DIM];
__device__ __align__(16) float g_fWat[DIM * DIM];     // [k][i] = f_W[i*256 + k] (reads part)

__device__ __forceinline__ float sigmoidf_(float x) { return 1.f / (1.f + __expf(-x)); }

// =====================================================================
// w table: softmax(k_emb[c] · Mk^T) over 50 slots; 125 CTAs
// =====================================================================
__global__ void k_wtable(const float* __restrict__ k_emb, const float* __restrict__ Mk) {
    __shared__ float mksh[DIM * 65];   // padded transpose, conflict-free
    __shared__ float ksh[4 * DIM];
    __shared__ float gmax[8], gsum[8];
    int tid = threadIdx.x;
    int c0 = blockIdx.x * 16;
    int m = tid & 63, cg = tid >> 6, wh = (tid >> 5) & 1;
    for (int i = tid; i < MM * DIM; i += 256) {
        int mm = i >> 7, j = i & 127;
        mksh[j * 65 + mm] = Mk[i];
    }
    for (int cl = 0; cl < 16; cl += 4) {
        int c = c0 + cl + cg;
        __syncthreads();
        for (int j = tid; j < 4 * DIM; j += 256)
            ksh[j] = k_emb[(c0 + cl + (j >> 7)) * DIM + (j & 127)];
        __syncthreads();
        float acc = 0.f;
        if (m < MM) {
            #pragma unroll 8
            for (int j = 0; j < DIM; j++) acc = fmaf(ksh[cg * DIM + j], mksh[j * 65 + m], acc);
        }
        float lg = (m < MM) ? acc : -1e30f;
        float mx = lg;
        #pragma unroll
        for (int off = 16; off; off >>= 1) mx = fmaxf(mx, __shfl_xor_sync(~0u, mx, off));
        if ((tid & 31) == 0) gmax[cg * 2 + wh] = mx;
        __syncthreads();
        mx = fmaxf(gmax[cg * 2], gmax[cg * 2 + 1]);
        float ex = (m < MM) ? __expf(lg - mx) : 0.f;
        float sv = ex;
        #pragma unroll
        for (int off = 16; off; off >>= 1) sv += __shfl_xor_sync(~0u, sv, off);
        if ((tid & 31) == 0) gsum[cg * 2 + wh] = sv;
        __syncthreads();
        float s = gsum[cg * 2] + gsum[cg * 2 + 1];
        if (m < MP) g_w[c * MP + m] = ex / s;
    }
}

// =====================================================================
// e/a table: 4000 x 256 GEMM (K=128) + activations; 125 CTAs; f32x2
// =====================================================================
__global__ void k_ea(const float* __restrict__ v_emb, const float* __restrict__ e_b,
                     const float* __restrict__ a_b,
                     const float* __restrict__ e_W, const float* __restrict__ a_W) {
    __shared__ float Xs[32 * DIM];
    __shared__ __align__(16) float Ws[16 * 260];
    int row0 = blockIdx.x * 32;
    int tid = threadIdx.x;
    int tx = tid & 31, ty = tid >> 5;       // col pair-group = tx*4 pairs, rows ty*4..
    for (int i = tid; i < 32 * DIM; i += 256) Xs[i] = v_emb[row0 * DIM + i];
    u64 acc[4][4];
    #pragma unroll
    for (int u = 0; u < 4; u++)
        #pragma unroll
        for (int v = 0; v < 4; v++) acc[u][v] = 0ull;
    for (int kc = 0; kc < DIM; kc += 16) {
        __syncthreads();
        for (int i = tid; i < 16 * 256; i += 256) {
            int kk = i & 15, c = i >> 4;    // coalesced read, transposed write
            float v = (c < DIM) ? e_W[c * DIM + kc + kk] : a_W[(c - DIM) * DIM + kc + kk];
            Ws[kk * 260 + c] = v;
        }
        __syncthreads();
        #pragma unroll
        for (int kk = 0; kk < 16; kk++) {
            u64 xv[4];
            #pragma unroll
            for (int u = 0; u < 4; u++) {
                float x = Xs[(ty * 4 + u) * DIM + kc + kk];
                xv[u] = pk2(x, x);
            }
            ulonglong2 wA = *(const ulonglong2*)&Ws[kk * 260 + tx * 8];
            ulonglong2 wB = *(const ulonglong2*)&Ws[kk * 260 + tx * 8 + 4];
            #pragma unroll
            for (int u = 0; u < 4; u++) {
                acc[u][0] = fma2(xv[u], wA.x, acc[u][0]);
                acc[u][1] = fma2(xv[u], wA.y, acc[u][1]);
                acc[u][2] = fma2(xv[u], wB.x, acc[u][2]);
                acc[u][3] = fma2(xv[u], wB.y, acc[u][3]);
            }
        }
    }
    int col = tx * 8;
    float barr[8];
    #pragma unroll
    for (int v = 0; v < 8; v++) {
        int cc = col + v;
        barr[v] = (cc < DIM) ? e_b[cc] : a_b[cc - DIM];
    }
    #pragma unroll
    for (int u = 0; u < 4; u++) {
        float z[8], o[8];
        upk2(z[0], z[1], acc[u][0]); upk2(z[2], z[3], acc[u][1]);
        upk2(z[4], z[5], acc[u][2]); upk2(z[6], z[7], acc[u][3]);
        #pragma unroll
        for (int v = 0; v < 8; v++) {
            float zz = z[v] + barr[v];
            o[v] = (col + v < DIM) ? sigmoidf_(zz) : tanhf(zz);
        }
        int r = row0 + ty * 4 + u;
        *(float4*)&g_ea[r * 256 + col]     = make_float4(o[0], o[1], o[2], o[3]);
        *(float4*)&g_ea[r * 256 + col + 4] = make_float4(o[4], o[5], o[6], o[7]);
    }
}

// =====================================================================
// kf table (63 CTAs) + f_W(reads-half) transpose (8 CTAs); f32x2
// =====================================================================
__global__ void k_kfT(const float* __restrict__ k_emb, const float* __restrict__ f_b,
                      const float* __restrict__ f_W) {
    __shared__ float Xs[32 * DIM];
    __shared__ __align__(16) float Ws[16 * 132];
    int bid = blockIdx.x;
    int tid = threadIdx.x;
    if (bid >= 63) {
        int base = (bid - 63) * 2048;
        #pragma unroll
        for (int j = 0; j < 8; j++) {
            int idx = base + j * 256 + tid;
            int k = idx >> 7, ii = idx & 127;
            g_fWat[idx] = f_W[ii * 256 + k];
        }
        return;
    }
    int row0 = bid * 32;
    for (int i = tid; i < 32 * DIM; i += 256) {
        int rr = i >> 7;
        Xs[i] = (row0 + rr < NUM_C) ? k_emb[row0 * DIM + i] : 0.f;
    }
    int tx = tid & 31, ty = tid >> 5;      // col = tx*4
    u64 acc[4][2];
    #pragma unroll
    for (int u = 0; u < 4; u++) { acc[u][0] = 0ull; acc[u][1] = 0ull; }
    for (int kc = 0; kc < DIM; kc += 16) {
        __syncthreads();
        for (int i = tid; i < 16 * DIM; i += 256) {
            int kk = i & 15, col = i >> 4;
            Ws[kk * 132 + col] = f_W[col * 256 + 128 + kc + kk];
        }
        __syncthreads();
        #pragma unroll
        for (int kk = 0; kk < 16; kk++) {
            ulonglong2 w0 = *(const ulonglong2*)&Ws[kk * 132 + tx * 4];
            #pragma unroll
            for (int u = 0; u < 4; u++) {
                float x = Xs[(ty * 4 + u) * DIM + kc + kk];
                u64 xb = pk2(x, x);
                acc[u][0] = fma2(xb, w0.x, acc[u][0]);
                acc[u][1] = fma2(xb, w0.y, acc[u][1]);
            }
        }
    }
    int col = tx * 4;
    float b0 = f_b[col], b1 = f_b[col + 1], b2 = f_b[col + 2], b3 = f_b[col + 3];
    #pragma unroll
    for (int u = 0; u < 4; u++) {
        int r = row0 + ty * 4 + u;
        if (r < NUM_C) {
            float z0, z1, z2, z3;
            upk2(z0, z1, acc[u][0]); upk2(z2, z3, acc[u][1]);
            *(float4*)&g_kf[r * DIM + col] =
                make_float4(z0 + b0, z1 + b1, z2 + b2, z3 + b3);
        }
    }
}

// =====================================================================
// Sequential scan: 128 CTAs = 64 batches x 2 d-halves; 1 sync/step;
// depth-3 prefetch; deferred reduction; f32x2 recurrence.
// =====================================================================
__global__ void k_scan(const int* __restrict__ skill, const int* __restrict__ answer,
                       const float* __restrict__ Mv0) {
    __shared__ int s_sk[TT], s_x[TT];
    __shared__ __align__(16) float w_sh[4][MP];
    __shared__ __align__(16) float e_sh[4][64];
    __shared__ __align__(16) float a_sh[4][64];
    __shared__ __align__(16) float red[2][8][64];
    int b = blockIdx.x >> 1;
    int dbase = (blockIdx.x & 1) * 64;
    int tid = threadIdx.x;
    int dgi = tid & 31, mg = tid >> 5;
    int d0 = dbase + dgi * 2;

    for (int t = tid; t < TT; t += 256) {
        int s = skill[b * TT + t];
        int aa = answer[b * TT + t];
        if (aa > 1) aa = 1;
        s_sk[t] = s;
        s_x[t] = s + NUM_C * aa;
    }

    u64 mv[7];
    #pragma unroll
    for (int i = 0; i < 7; i++) {
        int m = mg * 7 + i;
        if (m < MM) {
            float2 v = *(const float2*)&Mv0[m * DIM + d0];
            mv[i] = pk2(v.x, v.y);
        } else mv[i] = 0ull;
    }
    __syncthreads();   // s_sk/s_x visible

    bool lp = tid < 184;
    float pfA = 0.f, pfB = 0.f;
    if (lp) {
        float v0, v1, v2;
        if (tid < MP) {
            v0 = g_w[s_sk[0] * MP + tid];
            v1 = g_w[s_sk[1] * MP + tid];
            v2 = g_w[s_sk[2] * MP + tid];
            w_sh[0][tid] = v0;
        } else if (tid < 120) {
            int o = dbase + (tid - 56);
            v0 = g_ea[s_x[0] * 256 + o];
            v1 = g_ea[s_x[1] * 256 + o];
            v2 = g_ea[s_x[2] * 256 + o];
            e_sh[0][tid - 56] = v0;
        } else {
            int o = 128 + dbase + (tid - 120);
            v0 = g_ea[s_x[0] * 256 + o];
            v1 = g_ea[s_x[1] * 256 + o];
            v2 = g_ea[s_x[2] * 256 + o];
            a_sh[0][tid - 120] = v0;
        }
        pfA = v1; pfB = v2;
    }
    __syncthreads();

    for (int t = 0; t < TT; t++) {
        int cur = t & 3;
        float2 e2 = *(const float2*)&e_sh[cur][dgi * 2];
        float2 a2 = *(const float2*)&a_sh[cur][dgi * 2];
        u64 negE = pk2(-e2.x, -e2.y);
        u64 A2 = pk2(a2.x, a2.y);
        u64 acc2 = 0ull;
        #pragma unroll
        for (int i = 0; i < 7; i++) {
            float wm = w_sh[cur][mg * 7 + i];
            u64 W2 = pk2(wm, wm);
            acc2 = fma2(W2, mv[i], acc2);                  // read uses PRE-update Mv
            mv[i] = fma2(W2, fma2(negE, mv[i], A2), mv[i]);
        }
        *(u64*)&red[t & 1][mg][dgi * 2] = acc2;
        if (lp) {                                           // STS: data for t+1
            float pv = (t & 1) ? pfB : pfA;
            int nb = (t + 1) & 3;
            if (tid < MP)       w_sh[nb][tid] = pv;
            else if (tid < 120) e_sh[nb][tid - 56] = pv;
            else                a_sh[nb][tid - 120] = pv;
        }
        if (lp && t + 3 < TT) {                             // LDG: fetch t+3
            float nv;
            if (tid < MP)       nv = g_w[s_sk[t + 3] * MP + tid];
            else if (tid < 120) nv = g_ea[s_x[t + 3] * 256 + dbase + (tid - 56)];
            else                nv = g_ea[s_x[t + 3] * 256 + 128 + dbase + (tid - 120)];
            if (t & 1) pfB = nv; else pfA = nv;
        }
        if (t > 0 && tid < 64) {                            // deferred reduction t-1
            float s = 0.f;
            #pragma unroll
            for (int i = 0; i < 8; i++) s += red[(t - 1) & 1][i][tid];
            g_reads[(b * TT + t - 1) * DIM + dbase + tid] = s;
        }
        __syncthreads();
    }
    if (tid < 64) {
        float s = 0.f;
        #pragma unroll
        for (int i = 0; i < 8; i++) s += red[(TT - 1) & 1][i][tid];
        g_reads[(b * TT + TT - 1) * DIM + dbase + tid] = s;
    }
}

// =====================================================================
// fpred: 398 CTAs x 32 rows. Entire fWat resident in smem (64KB),
// zero mainloop syncs, f32x2 inner loop, fused kf + tanh + gathered pred.
// =====================================================================
#define FP_SMEM ((32 * 129 + 128 * 128) * 4)
__global__ __launch_bounds__(256) void k_fpred(const int* __restrict__ skill,
                                               const float* __restrict__ p_W,
                                               const float* __restrict__ p_b,
                                               float* __restrict__ out) {
    extern __shared__ __align__(16) float dsm[];
    float* Xs = dsm;               // [32][129] reads tile; later reused for f
    float* Ws = dsm + 32 * 129;    // [128][128] full fWat
    __shared__ int s_kf[32], s_nx[32], roff[32];
    int row0 = blockIdx.x * 32;
    int tid = threadIdx.x;
    if (tid < 32) {
        int r = row0 + tid;
        int bb = r / 199;
        int t = r - bb * 199;
        s_kf[tid] = skill[bb * TT + t];
        s_nx[tid] = skill[bb * TT + t + 1];
        roff[tid] = (bb * TT + t) * DIM;
    }
    for (int i = tid * 4; i < 128 * 128; i += 1024)
        *(float4*)&Ws[i] = *(const float4*)&g_fWat[i];
    __syncthreads();               // roff ready
    for (int i = tid; i < 32 * DIM; i += 256) {
        int rr = i >> 7, k = i & 127;
        Xs[rr * 129 + k] = g_reads[roff[rr] + k];
    }
    __syncthreads();
    int tx = tid & 15, ty = tid >> 4;    // cols tx*8.., rows ty*2..+1
    u64 acc[2][4];
    #pragma unroll
    for (int u = 0; u < 2; u++)
        #pragma unroll
        for (int v = 0; v < 4; v++) acc[u][v] = 0ull;
    #pragma unroll 8
    for (int k = 0; k < 128; k++) {
        float x0 = Xs[(ty * 2) * 129 + k];
        float x1 = Xs[(ty * 2 + 1) * 129 + k];
        u64 xb0 = pk2(x0, x0), xb1 = pk2(x1, x1);
        ulonglong2 wA = *(const ulonglong2*)&Ws[k * 128 + tx * 8];
        ulonglong2 wB = *(const ulonglong2*)&Ws[k * 128 + tx * 8 + 4];
        acc[0][0] = fma2(xb0, wA.x, acc[0][0]);
        acc[0][1] = fma2(xb0, wA.y, acc[0][1]);
        acc[0][2] = fma2(xb0, wB.x, acc[0][2]);
        acc[0][3] = fma2(xb0, wB.y, acc[0][3]);
        acc[1][0] = fma2(xb1, wA.x, acc[1][0]);
        acc[1][1] = fma2(xb1, wA.y, acc[1][1]);
        acc[1][2] = fma2(xb1, wB.x, acc[1][2]);
        acc[1][3] = fma2(xb1, wB.y, acc[1][3]);
    }
    __syncthreads();   // all Xs reads done -> overwrite with f
    int col = tx * 8;
    #pragma unroll
    for (int u = 0; u < 2; u++) {
        int row = ty * 2 + u;
        int sc = s_kf[row];
        float4 k0 = *(const float4*)&g_kf[sc * DIM + col];
        float4 k1 = *(const float4*)&g_kf[sc * DIM + col + 4];
        float z[8];
        upk2(z[0], z[1], acc[u][0]); upk2(z[2], z[3], acc[u][1]);
        upk2(z[4], z[5], acc[u][2]); upk2(z[6], z[7], acc[u][3]);
        Xs[row * 129 + col + 0] = tanhf(z[0] + k0.x);
        Xs[row * 129 + col + 1] = tanhf(z[1] + k0.y);
        Xs[row * 129 + col + 2] = tanhf(z[2] + k0.z);
        Xs[row * 129 + col + 3] = tanhf(z[3] + k0.w);
        Xs[row * 129 + col + 4] = tanhf(z[4] + k1.x);
        Xs[row * 129 + col + 5] = tanhf(z[5] + k1.y);
        Xs[row * 129 + col + 6] = tanhf(z[6] + k1.z);
        Xs[row * 129 + col + 7] = tanhf(z[7] + k1.w);
    }
    __syncthreads();
    int wid = tid >> 5, lane = tid & 31;
    for (int rr = wid * 4; rr < wid * 4 + 4; rr++) {
        int ns = s_nx[rr];
        int idx = (ns < NUM_C) ? ns : (NUM_C - 1);
        const float* pw = p_W + idx * DIM;
        float a = 0.f;
        #pragma unroll
        for (int q = 0; q < 4; q++) a = fmaf(Xs[rr * 129 + lane + 32 * q], pw[lane + 32 * q], a);
        #pragma unroll
        for (int off = 16; off; off >>= 1) a += __shfl_xor_sync(~0u, a, off);
        if (lane == 0) {
            float pr = sigmoidf_(a + p_b[idx]);
            out[row0 + rr] = (ns < NUM_C) ? pr : 0.f;
        }
    }
}

// ---------------- launch: forked-capture stream graph ----------------------
extern "C" void kernel_launch(void* const* d_in, const int* in_sizes, int n_in,
                              void* d_out, int out_size) {
    const int*   skill  = (const int*)d_in[0];
    const int*   answer = (const int*)d_in[1];
    const float* k_emb  = (const float*)d_in[2];
    const float* v_emb  = (const float*)d_in[3];
    const float* Mk     = (const float*)d_in[4];
    const float* Mv0    = (const float*)d_in[5];
    const float* f_W    = (const float*)d_in[6];
    const float* f_b    = (const float*)d_in[7];
    const float* p_W    = (const float*)d_in[8];
    const float* p_b    = (const float*)d_in[9];
    const float* e_W    = (const float*)d_in[10];
    const float* e_b    = (const float*)d_in[11];
    const float* a_W    = (const float*)d_in[12];
    const float* a_b    = (const float*)d_in[13];
    float* out = (float*)d_out;

    static cudaStream_t sA = nullptr, sB = nullptr, sC = nullptr;
    static cudaEvent_t evR = nullptr, evA = nullptr, evB = nullptr, evC = nullptr;
    if (!sA) {   // first call = correctness run (not captured): safe to create
        cudaStreamCreateWithFlags(&sA, cudaStreamNonBlocking);
        cudaStreamCreateWithFlags(&sB, cudaStreamNonBlocking);
        cudaStreamCreateWithFlags(&sC, cudaStreamNonBlocking);
        cudaEventCreateWithFlags(&evR, cudaEventDisableTiming);
        cudaEventCreateWithFlags(&evA, cudaEventDisableTiming);
        cudaEventCreateWithFlags(&evB, cudaEventDisableTiming);
        cudaEventCreateWithFlags(&evC, cudaEventDisableTiming);
        cudaFuncSetAttribute(k_fpred, cudaFuncAttributeMaxDynamicSharedMemorySize, FP_SMEM);
    }

    cudaEventRecord(evR, 0);
    cudaStreamWaitEvent(sA, evR, 0);
    cudaStreamWaitEvent(sB, evR, 0);
    cudaStreamWaitEvent(sC, evR, 0);

    k_wtable<<<125, 256, 0, sA>>>(k_emb, Mk);
    k_ea    <<<125, 256, 0, sB>>>(v_emb, e_b, a_b, e_W, a_W);
    k_kfT   <<<71, 256, 0, sC>>>(k_emb, f_b, f_W);      // overlaps scan

    cudaEventRecord(evA, sA);
    cudaEventRecord(evB, sB);
    cudaEventRecord(evC, sC);

    cudaStreamWaitEvent(0, evA, 0);
    cudaStreamWaitEvent(0, evB, 0);
    k_scan<<<128, 256>>>(skill, answer, Mv0);

    cudaStreamWaitEvent(0, evC, 0);
    k_fpred<<<398, 256, FP_SMEM>>>(skill, p_W, p_b, out);
}

// round 6
// speedup vs baseline: 2.4927x; 2.4927x over previous
#include <cuda_runtime.h>

#define BATCH 64
#define TT    200
#define NUM_C 2000
#define DIM   128
#define MM    50
#define MP    56          // M padded; rows 50..55 have w=0 (inert)
#define NX    4000        // distinct x = skill + 2000*answer

// ---------------- scratch (device globals; no allocation allowed) ----------
__device__ __align__(16) float g_w[NUM_C * MP];       // softmax(k·Mk^T) per skill id
__device__ __align__(16) float g_ea[NX * 256];        // [x][0:128]=e, [128:256]=a
__device__ __align__(16) float g_kf[NUM_C * DIM];     // k-part of f GEMM + f_b folded
__device__ __align__(16) float g_reads[BATCH * TT * DIM];
__device__ __align__(16) float g_fWat[DIM * DIM];     // [k][i] = f_W[i*256 + k] (reads part)

__device__ __forceinline__ float sigmoidf_(float x) { return 1.f / (1.f + __expf(-x)); }

// =====================================================================
// w table: softmax(k_emb[c] · Mk^T) over 50 slots; 125 CTAs
// =====================================================================
__global__ void k_wtable(const float* __restrict__ k_emb, const float* __restrict__ Mk) {
    __shared__ float mksh[DIM * 65];   // padded transpose, conflict-free
    __shared__ float ksh[4 * DIM];
    __shared__ float gmax[8], gsum[8];
    int tid = threadIdx.x;
    int c0 = blockIdx.x * 16;
    int m = tid & 63, cg = tid >> 6, wh = (tid >> 5) & 1;
    for (int i = tid; i < MM * DIM; i += 256) {
        int mm = i >> 7, j = i & 127;
        mksh[j * 65 + mm] = Mk[i];
    }
    for (int cl = 0; cl < 16; cl += 4) {
        int c = c0 + cl + cg;
        __syncthreads();
        for (int j = tid; j < 4 * DIM; j += 256)
            ksh[j] = k_emb[(c0 + cl + (j >> 7)) * DIM + (j & 127)];
        __syncthreads();
        float acc = 0.f;
        if (m < MM) {
            #pragma unroll 8
            for (int j = 0; j < DIM; j++) acc = fmaf(ksh[cg * DIM + j], mksh[j * 65 + m], acc);
        }
        float lg = (m < MM) ? acc : -1e30f;
        float mx = lg;
        #pragma unroll
        for (int off = 16; off; off >>= 1) mx = fmaxf(mx, __shfl_xor_sync(~0u, mx, off));
        if ((tid & 31) == 0) gmax[cg * 2 + wh] = mx;
        __syncthreads();
        mx = fmaxf(gmax[cg * 2], gmax[cg * 2 + 1]);
        float ex = (m < MM) ? __expf(lg - mx) : 0.f;
        float sv = ex;
        #pragma unroll
        for (int off = 16; off; off >>= 1) sv += __shfl_xor_sync(~0u, sv, off);
        if ((tid & 31) == 0) gsum[cg * 2 + wh] = sv;
        __syncthreads();
        float s = gsum[cg * 2] + gsum[cg * 2 + 1];
        if (m < MP) g_w[c * MP + m] = ex / s;
    }
}

// =====================================================================
// e/a table: 4000 x 256 GEMM (K=128) + activations; 125 CTAs; plain FMA
// Weight transpose folded into smem tile load (coalesced LDG, padded STS).
// =====================================================================
__global__ void k_ea(const float* __restrict__ v_emb, const float* __restrict__ e_b,
                     const float* __restrict__ a_b,
                     const float* __restrict__ e_W, const float* __restrict__ a_W) {
    __shared__ float Xs[32 * DIM];
    __shared__ __align__(16) float Ws[16 * 260];
    int row0 = blockIdx.x * 32;
    int tid = threadIdx.x;
    int tx = tid & 31, ty = tid >> 5;       // col = tx*8, rows ty*4..+3
    for (int i = tid; i < 32 * DIM; i += 256) Xs[i] = v_emb[row0 * DIM + i];
    float acc[4][8];
    #pragma unroll
    for (int u = 0; u < 4; u++)
        #pragma unroll
        for (int v = 0; v < 8; v++) acc[u][v] = 0.f;
    for (int kc = 0; kc < DIM; kc += 16) {
        __syncthreads();
        for (int i = tid; i < 16 * 256; i += 256) {
            int kk = i & 15, c = i >> 4;    // coalesced read, transposed write
            float v = (c < DIM) ? e_W[c * DIM + kc + kk] : a_W[(c - DIM) * DIM + kc + kk];
            Ws[kk * 260 + c] = v;
        }
        __syncthreads();
        #pragma unroll
        for (int kk = 0; kk < 16; kk++) {
            float xv[4];
            #pragma unroll
            for (int u = 0; u < 4; u++) xv[u] = Xs[(ty * 4 + u) * DIM + kc + kk];
            float4 w0 = *(const float4*)&Ws[kk * 260 + tx * 8];
            float4 w1 = *(const float4*)&Ws[kk * 260 + tx * 8 + 4];
            #pragma unroll
            for (int u = 0; u < 4; u++) {
                acc[u][0] = fmaf(xv[u], w0.x, acc[u][0]);
                acc[u][1] = fmaf(xv[u], w0.y, acc[u][1]);
                acc[u][2] = fmaf(xv[u], w0.z, acc[u][2]);
                acc[u][3] = fmaf(xv[u], w0.w, acc[u][3]);
                acc[u][4] = fmaf(xv[u], w1.x, acc[u][4]);
                acc[u][5] = fmaf(xv[u], w1.y, acc[u][5]);
                acc[u][6] = fmaf(xv[u], w1.z, acc[u][6]);
                acc[u][7] = fmaf(xv[u], w1.w, acc[u][7]);
            }
        }
    }
    int col = tx * 8;
    float barr[8];
    #pragma unroll
    for (int v = 0; v < 8; v++) {
        int cc = col + v;
        barr[v] = (cc < DIM) ? e_b[cc] : a_b[cc - DIM];
    }
    #pragma unroll
    for (int u = 0; u < 4; u++) {
        float o[8];
        #pragma unroll
        for (int v = 0; v < 8; v++) {
            float z = acc[u][v] + barr[v];
            o[v] = (col + v < DIM) ? sigmoidf_(z) : tanhf(z);
        }
        int r = row0 + ty * 4 + u;
        *(float4*)&g_ea[r * 256 + col]     = make_float4(o[0], o[1], o[2], o[3]);
        *(float4*)&g_ea[r * 256 + col + 4] = make_float4(o[4], o[5], o[6], o[7]);
    }
}

// =====================================================================
// kf table (63 CTAs) + f_W(reads-half) transpose (8 CTAs); plain FMA
// =====================================================================
__global__ void k_kfT(const float* __restrict__ k_emb, const float* __restrict__ f_b,
                      const float* __restrict__ f_W) {
    __shared__ float Xs[32 * DIM];
    __shared__ __align__(16) float Ws[16 * 132];
    int bid = blockIdx.x;
    int tid = threadIdx.x;
    if (bid >= 63) {
        int base = (bid - 63) * 2048;
        #pragma unroll
        for (int j = 0; j < 8; j++) {
            int idx = base + j * 256 + tid;
            int k = idx >> 7, ii = idx & 127;
            g_fWat[idx] = f_W[ii * 256 + k];
        }
        return;
    }
    int row0 = bid * 32;
    for (int i = tid; i < 32 * DIM; i += 256) {
        int rr = i >> 7;
        Xs[i] = (row0 + rr < NUM_C) ? k_emb[row0 * DIM + i] : 0.f;
    }
    int tx = tid & 31, ty = tid >> 5;      // col = tx*4
    float acc[4][4];
    #pragma unroll
    for (int u = 0; u < 4; u++)
        #pragma unroll
        for (int v = 0; v < 4; v++) acc[u][v] = 0.f;
    for (int kc = 0; kc < DIM; kc += 16) {
        __syncthreads();
        for (int i = tid; i < 16 * DIM; i += 256) {
            int kk = i & 15, col = i >> 4;
            Ws[kk * 132 + col] = f_W[col * 256 + 128 + kc + kk];
        }
        __syncthreads();
        #pragma unroll
        for (int kk = 0; kk < 16; kk++) {
            float4 w0 = *(const float4*)&Ws[kk * 132 + tx * 4];
            #pragma unroll
            for (int u = 0; u < 4; u++) {
                float x = Xs[(ty * 4 + u) * DIM + kc + kk];
                acc[u][0] = fmaf(x, w0.x, acc[u][0]);
                acc[u][1] = fmaf(x, w0.y, acc[u][1]);
                acc[u][2] = fmaf(x, w0.z, acc[u][2]);
                acc[u][3] = fmaf(x, w0.w, acc[u][3]);
            }
        }
    }
    int col = tx * 4;
    float b0 = f_b[col], b1 = f_b[col + 1], b2 = f_b[col + 2], b3 = f_b[col + 3];
    #pragma unroll
    for (int u = 0; u < 4; u++) {
        int r = row0 + ty * 4 + u;
        if (r < NUM_C)
            *(float4*)&g_kf[r * DIM + col] =
                make_float4(acc[u][0] + b0, acc[u][1] + b1, acc[u][2] + b2, acc[u][3] + b3);
    }
}

// =====================================================================
// Sequential scan: 128 CTAs = 64 batches x 2 d-halves, 256 threads.
// Warp-local reduction (shfl), ONE sync/step, depth-4 prefetch with
// compile-time register rotation (t-loop unrolled x4).
// Lane map: ms = lane>>3 (m-group of 14), ds = lane&7; thread owns
// 14 m x 1 d, d = dbase + wid*8 + ds.
// =====================================================================
__global__ void k_scan(const int* __restrict__ skill, const int* __restrict__ answer,
                       const float* __restrict__ Mv0) {
    __shared__ int s_sk[TT], s_x[TT];
    __shared__ __align__(16) float w_sh[4][MP];
    __shared__ __align__(16) float e_sh[4][64];
    __shared__ __align__(16) float a_sh[4][64];
    int b = blockIdx.x >> 1;
    int dbase = (blockIdx.x & 1) * 64;
    int tid = threadIdx.x;
    int wid = tid >> 5, lane = tid & 31;
    int ms = lane >> 3, ds = lane & 7;
    int dd = wid * 8 + ds;                 // 0..63 within half

    for (int t = tid; t < TT; t += 256) {
        int s = skill[b * TT + t];
        int aa = answer[b * TT + t];
        if (aa > 1) aa = 1;
        s_sk[t] = s;
        s_x[t] = s + NUM_C * aa;
    }

    float mv[14];
    #pragma unroll
    for (int i = 0; i < 14; i++) {
        int m = ms * 14 + i;
        mv[i] = (m < MM) ? Mv0[m * DIM + dbase + dd] : 0.f;
    }
    __syncthreads();   // s_sk/s_x visible

    bool lp = tid < 184;   // gather roles: <56 w, <120 e, <184 a
    float pfR[4];          // pfR[s&3] holds gathered value for step s
    pfR[0] = 0.f; pfR[1] = 0.f; pfR[2] = 0.f; pfR[3] = 0.f;
    if (lp) {
        float v0;
        if (tid < MP) {
            v0      = g_w[s_sk[0] * MP + tid];
            pfR[1]  = g_w[s_sk[1] * MP + tid];
            pfR[2]  = g_w[s_sk[2] * MP + tid];
            pfR[3]  = g_w[s_sk[3] * MP + tid];
            w_sh[0][tid] = v0;
        } else if (tid < 120) {
            int o = dbase + (tid - 56);
            v0      = g_ea[s_x[0] * 256 + o];
            pfR[1]  = g_ea[s_x[1] * 256 + o];
            pfR[2]  = g_ea[s_x[2] * 256 + o];
            pfR[3]  = g_ea[s_x[3] * 256 + o];
            e_sh[0][tid - 56] = v0;
        } else {
            int o = 128 + dbase + (tid - 120);
            v0      = g_ea[s_x[0] * 256 + o];
            pfR[1]  = g_ea[s_x[1] * 256 + o];
            pfR[2]  = g_ea[s_x[2] * 256 + o];
            pfR[3]  = g_ea[s_x[3] * 256 + o];
            a_sh[0][tid - 120] = v0;
        }
    }
    __syncthreads();

    int outbase = (b * TT) * DIM + dbase + dd;

    for (int t0 = 0; t0 < TT; t0 += 4) {
        #pragma unroll
        for (int q = 0; q < 4; q++) {
            int t = t0 + q;
            // ---- compute step t from buffers[q] ----
            float e = e_sh[q][dd];
            float a = a_sh[q][dd];
            float acc = 0.f;
            #pragma unroll
            for (int i = 0; i < 14; i++) {
                float wm = w_sh[q][ms * 14 + i];
                acc = fmaf(wm, mv[i], acc);                      // PRE-update read
                mv[i] = fmaf(wm, fmaf(-e, mv[i], a), mv[i]);
            }
            acc += __shfl_xor_sync(~0u, acc, 8);
            acc += __shfl_xor_sync(~0u, acc, 16);
            if (ms == 0) g_reads[outbase + t * DIM] = acc;
            // ---- STS buffers for step t+1 (value loaded at t-3) ----
            if (lp && t + 1 < TT) {
                float pv = pfR[(q + 1) & 3];
                if (tid < MP)       w_sh[(q + 1) & 3][tid] = pv;
                else if (tid < 120) e_sh[(q + 1) & 3][tid - 56] = pv;
                else                a_sh[(q + 1) & 3][tid - 120] = pv;
            }
            // ---- LDG gather for step t+4 into just-freed slot q ----
            if (lp && t + 4 < TT) {
                float nv;
                if (tid < MP)       nv = g_w[s_sk[t + 4] * MP + tid];
                else if (tid < 120) nv = g_ea[s_x[t + 4] * 256 + dbase + (tid - 56)];
                else                nv = g_ea[s_x[t + 4] * 256 + 128 + dbase + (tid - 120)];
                pfR[q] = nv;
            }
            __syncthreads();
        }
    }
}

// =====================================================================
// fpred (R1-proven): f = tanh(reads@fWat + kf[skill]); gathered pred.
// 199 CTAs x 64 rows.
// =====================================================================
__global__ void k_fpred(const int* __restrict__ skill, const float* __restrict__ p_W,
                        const float* __restrict__ p_b, float* __restrict__ out) {
    __shared__ float Xs[64][130];                 // reads tile; later reused for f
    __shared__ __align__(16) float Ws[16][DIM];
    __shared__ int s_kf[64], s_nx[64], roff[64];
    int row0 = blockIdx.x * 64;
    int tid = threadIdx.x;
    if (tid < 64) {
        int r = row0 + tid;
        int b = r / 199;
        int t = r - b * 199;
        s_kf[tid] = skill[b * TT + t];
        s_nx[tid] = skill[b * TT + t + 1];
        roff[tid] = (b * TT + t) * DIM;
    }
    __syncthreads();
    for (int i = tid; i < 64 * DIM; i += 256) {
        int rr = i >> 7, k = i & 127;
        Xs[rr][k] = g_reads[roff[rr] + k];
    }
    int tx = tid & 15, ty = tid >> 4;   // col = tx*8, rows = ty*4..
    float acc[4][8];
    #pragma unroll
    for (int u = 0; u < 4; u++)
        #pragma unroll
        for (int v = 0; v < 8; v++) acc[u][v] = 0.f;
    for (int kc = 0; kc < DIM; kc += 16) {
        __syncthreads();
        for (int i = tid; i < 16 * DIM; i += 256)
            Ws[i >> 7][i & 127] = g_fWat[(kc + (i >> 7)) * DIM + (i & 127)];
        __syncthreads();
        #pragma unroll
        for (int kk = 0; kk < 16; kk++) {
            float xv[4];
            #pragma unroll
            for (int u = 0; u < 4; u++) xv[u] = Xs[ty * 4 + u][kc + kk];
            float4 w0 = *(const float4*)&Ws[kk][tx * 8];
            float4 w1 = *(const float4*)&Ws[kk][tx * 8 + 4];
            #pragma unroll
            for (int u = 0; u < 4; u++) {
                acc[u][0] = fmaf(xv[u], w0.x, acc[u][0]);
                acc[u][1] = fmaf(xv[u], w0.y, acc[u][1]);
                acc[u][2] = fmaf(xv[u], w0.z, acc[u][2]);
                acc[u][3] = fmaf(xv[u], w0.w, acc[u][3]);
                acc[u][4] = fmaf(xv[u], w1.x, acc[u][4]);
                acc[u][5] = fmaf(xv[u], w1.y, acc[u][5]);
                acc[u][6] = fmaf(xv[u], w1.z, acc[u][6]);
                acc[u][7] = fmaf(xv[u], w1.w, acc[u][7]);
            }
        }
    }
    __syncthreads();   // everyone done reading Xs -> overwrite with f
    int col = tx * 8;
    #pragma unroll
    for (int u = 0; u < 4; u++) {
        int row = ty * 4 + u;
        int sc = s_kf[row];
        float4 k0 = *(const float4*)&g_kf[sc * DIM + col];
        float4 k1 = *(const float4*)&g_kf[sc * DIM + col + 4];
        Xs[row][col + 0] = tanhf(acc[u][0] + k0.x);
        Xs[row][col + 1] = tanhf(acc[u][1] + k0.y);
        Xs[row][col + 2] = tanhf(acc[u][2] + k0.z);
        Xs[row][col + 3] = tanhf(acc[u][3] + k0.w);
        Xs[row][col + 4] = tanhf(acc[u][4] + k1.x);
        Xs[row][col + 5] = tanhf(acc[u][5] + k1.y);
        Xs[row][col + 6] = tanhf(acc[u][6] + k1.z);
        Xs[row][col + 7] = tanhf(acc[u][7] + k1.w);
    }
    __syncthreads();
    int wid = tid >> 5, lane = tid & 31;
    for (int rr = wid * 8; rr < wid * 8 + 8; rr++) {
        int ns = s_nx[rr];
        int idx = (ns < NUM_C) ? ns : (NUM_C - 1);
        const float* pw = p_W + idx * DIM;
        float a = 0.f;
        #pragma unroll
        for (int q = 0; q < 4; q++) a = fmaf(Xs[rr][lane + 32 * q], pw[lane + 32 * q], a);
        #pragma unroll
        for (int off = 16; off; off >>= 1) a += __shfl_xor_sync(~0u, a, off);
        if (lane == 0) {
            float pr = sigmoidf_(a + p_b[idx]);
            out[row0 + rr] = (ns < NUM_C) ? pr : 0.f;
        }
    }
}

// ---------------- launch: forked-capture stream graph ----------------------
extern "C" void kernel_launch(void* const* d_in, const int* in_sizes, int n_in,
                              void* d_out, int out_size) {
    const int*   skill  = (const int*)d_in[0];
    const int*   answer = (const int*)d_in[1];
    const float* k_emb  = (const float*)d_in[2];
    const float* v_emb  = (const float*)d_in[3];
    const float* Mk     = (const float*)d_in[4];
    const float* Mv0    = (const float*)d_in[5];
    const float* f_W    = (const float*)d_in[6];
    const float* f_b    = (const float*)d_in[7];
    const float* p_W    = (const float*)d_in[8];
    const float* p_b    = (const float*)d_in[9];
    const float* e_W    = (const float*)d_in[10];
    const float* e_b    = (const float*)d_in[11];
    const float* a_W    = (const float*)d_in[12];
    const float* a_b    = (const float*)d_in[13];
    float* out = (float*)d_out;

    static cudaStream_t sA = nullptr, sB = nullptr, sC = nullptr;
    static cudaEvent_t evR = nullptr, evA = nullptr, evB = nullptr, evC = nullptr;
    if (!sA) {   // first call = correctness run (not captured): safe to create
        cudaStreamCreateWithFlags(&sA, cudaStreamNonBlocking);
        cudaStreamCreateWithFlags(&sB, cudaStreamNonBlocking);
        cudaStreamCreateWithFlags(&sC, cudaStreamNonBlocking);
        cudaEventCreateWithFlags(&evR, cudaEventDisableTiming);
        cudaEventCreateWithFlags(&evA, cudaEventDisableTiming);
        cudaEventCreateWithFlags(&evB, cudaEventDisableTiming);
        cudaEventCreateWithFlags(&evC, cudaEventDisableTiming);
    }

    cudaEventRecord(evR, 0);
    cudaStreamWaitEvent(sA, evR, 0);
    cudaStreamWaitEvent(sB, evR, 0);
    cudaStreamWaitEvent(sC, evR, 0);

    k_wtable<<<125, 256, 0, sA>>>(k_emb, Mk);
    k_ea    <<<125, 256, 0, sB>>>(v_emb, e_b, a_b, e_W, a_W);
    k_kfT   <<<71, 256, 0, sC>>>(k_emb, f_b, f_W);      // overlaps scan

    cudaEventRecord(evA, sA);
    cudaEventRecord(evB, sB);
    cudaEventRecord(evC, sC);

    cudaStreamWaitEvent(0, evA, 0);
    cudaStreamWaitEvent(0, evB, 0);
    k_scan<<<128, 256>>>(skill, answer, Mv0);

    cudaStreamWaitEvent(0, evC, 0);
    k_fpred<<<199, 256>>>(skill, p_W, p_b, out);
}